// round 17
// baseline (speedup 1.0000x reference)
#include <cuda_runtime.h>
#include <cuda_bf16.h>
#include <math.h>

// Problem constants
#define BATCH 256
#define TT    200
#define DIN   128
#define HH    256
#define OUTD  118
#define G3    768   // 3*H

typedef unsigned long long ull;
typedef unsigned int uint;

// packed fp32x2 helpers
#define FMA2(acc, a, b) \
    asm("fma.rn.f32x2 %0, %1, %2, %0;" : "+l"(acc) : "l"(a), "l"(b))
#define PACK2(d, f) \
    asm("mov.b64 %0, {%1, %1};" : "=l"(d) : "f"(f))
#define UNPACK2(lo, hi, v) \
    asm("mov.b64 {%0, %1}, %2;" : "=f"(lo), "=f"(hi) : "l"(v))

__device__ __forceinline__ uint f2tf32(float f) {
    uint u;
    asm("cvt.rna.tf32.f32 %0, %1;" : "=r"(u) : "f"(f));
    return u;
}

// ---------------- scratch (static device globals; no allocation) -------------
__device__ float g_gx[(size_t)BATCH * TT * G3];
__device__ float g_hseq[(size_t)BATCH * TT * HH];
__device__ float g_hA[BATCH * HH];
__device__ float g_hB[BATCH * HH];
__device__ float g_hfin[BATCH * HH];
__device__ int   g_flags[16 * 32];   // one flag per group, 128B padded

// ---------------------------------------------------------------------------
// tf32 tensor-core GEMM (unchanged from R4)
// ---------------------------------------------------------------------------
__global__ __launch_bounds__(256) void gemm_tf32_kernel(
    const float* __restrict__ A, const float* __restrict__ W,
    const float* __restrict__ bias, float* __restrict__ C,
    int M, int K)
{
    extern __shared__ uint smemU[];
    const int nb = blockIdx.x * 128;
    const int mb = blockIdx.y * 128;
    const int tid = threadIdx.x;
    const int wid = tid >> 5;
    const int lane = tid & 31;
    const int wm = wid & 1;
    const int wn = wid >> 1;
    const int r = lane >> 2;
    const int c = lane & 3;

    const float* gA = A + (size_t)mb * K;
    const float* gW = W + (size_t)nb * K;

    float acc[4][4][4];
#pragma unroll
    for (int i = 0; i < 4; i++)
#pragma unroll
        for (int j = 0; j < 4; j++)
#pragma unroll
            for (int q = 0; q < 4; q++) acc[i][j][q] = 0.f;

    const int nk = K >> 5;

    float4 pa[4], pb[4];
#pragma unroll
    for (int j = 0; j < 4; j++) {
        const int i = tid + j * 256;
        const int m = i >> 3;
        const int k4 = (i & 7) << 2;
        pa[j] = *(const float4*)(gA + (size_t)m * K + k4);
        pb[j] = *(const float4*)(gW + (size_t)m * K + k4);
    }

    for (int kc = 0; kc < nk; kc++) {
        uint* sA = smemU + (kc & 1) * 8192;
        uint* sB = sA + 4096;

#pragma unroll
        for (int j = 0; j < 4; j++) {
            const int i = tid + j * 256;
            const int m = i >> 3;
            const int k4 = (i & 7) << 2;
            const int base = m * 32 + ((((k4 >> 2) ^ (m & 7)) << 2));
            uint4 ua, ub;
            ua.x = f2tf32(pa[j].x); ua.y = f2tf32(pa[j].y);
            ua.z = f2tf32(pa[j].z); ua.w = f2tf32(pa[j].w);
            ub.x = f2tf32(pb[j].x); ub.y = f2tf32(pb[j].y);
            ub.z = f2tf32(pb[j].z); ub.w = f2tf32(pb[j].w);
            *(uint4*)(sA + base) = ua;
            *(uint4*)(sB + base) = ub;
        }
        __syncthreads();

        if (kc + 1 < nk) {
            const int kb = (kc + 1) << 5;
#pragma unroll
            for (int j = 0; j < 4; j++) {
                const int i = tid + j * 256;
                const int m = i >> 3;
                const int k4 = (i & 7) << 2;
                pa[j] = *(const float4*)(gA + (size_t)m * K + kb + k4);
                pb[j] = *(const float4*)(gW + (size_t)m * K + kb + k4);
            }
        }

#pragma unroll
        for (int kf = 0; kf < 4; kf++) {
            const int k0 = kf * 8 + c;
            const int k1 = k0 + 4;
            uint b0[4], b1[4];
#pragma unroll
            for (int nf = 0; nf < 4; nf++) {
                const int n = wn * 32 + nf * 8 + r;
                b0[nf] = sB[n * 32 + (((k0 >> 2) ^ (n & 7)) << 2) + (k0 & 3)];
                b1[nf] = sB[n * 32 + (((k1 >> 2) ^ (n & 7)) << 2) + (k1 & 3)];
            }
#pragma unroll
            for (int mf = 0; mf < 4; mf++) {
                const int m0 = wm * 64 + mf * 16 + r;
                const int m1 = m0 + 8;
                const uint a0 = sA[m0 * 32 + (((k0 >> 2) ^ (m0 & 7)) << 2) + (k0 & 3)];
                const uint a1 = sA[m1 * 32 + (((k0 >> 2) ^ (m1 & 7)) << 2) + (k0 & 3)];
                const uint a2 = sA[m0 * 32 + (((k1 >> 2) ^ (m0 & 7)) << 2) + (k1 & 3)];
                const uint a3 = sA[m1 * 32 + (((k1 >> 2) ^ (m1 & 7)) << 2) + (k1 & 3)];
#pragma unroll
                for (int nf = 0; nf < 4; nf++) {
                    asm("mma.sync.aligned.m16n8k8.row.col.f32.tf32.tf32.f32 "
                        "{%0,%1,%2,%3}, {%4,%5,%6,%7}, {%8,%9}, {%0,%1,%2,%3};"
                        : "+f"(acc[mf][nf][0]), "+f"(acc[mf][nf][1]),
                          "+f"(acc[mf][nf][2]), "+f"(acc[mf][nf][3])
                        : "r"(a0), "r"(a1), "r"(a2), "r"(a3),
                          "r"(b0[nf]), "r"(b1[nf]));
                }
            }
        }
        __syncthreads();
    }

#pragma unroll
    for (int nf = 0; nf < 4; nf++) {
        const int n = nb + wn * 32 + nf * 8 + c * 2;
        const float bb0 = bias[n], bb1 = bias[n + 1];
#pragma unroll
        for (int mf = 0; mf < 4; mf++) {
            const int m0 = mb + wm * 64 + mf * 16 + r;
            float2 v0, v1;
            v0.x = acc[mf][nf][0] + bb0; v0.y = acc[mf][nf][1] + bb1;
            v1.x = acc[mf][nf][2] + bb0; v1.y = acc[mf][nf][3] + bb1;
            *(float2*)(C + (size_t)m0 * G3 + n)       = v0;
            *(float2*)(C + (size_t)(m0 + 8) * G3 + n) = v1;
        }
    }
}

// ---------------------------------------------------------------------------
// Persistent GRU layer kernel — R15 structure + per-warp release:
// barrier (B) removed; each warp releases after its own stores (__syncwarp +
// lane0 red.release). Flag advances 32/step; consumers poll v >= 32*t.
// ---------------------------------------------------------------------------
#define SW_FLOATS (3 * 256 * 32)
#define SH_FLOATS (256 * 16)
#define SP_FLOATS (4 * 3 * 16 * 32)
#define LAYER_SMEM_FLOATS (SW_FLOATS + SH_FLOATS + SP_FLOATS)

__device__ __forceinline__ float sigm(float x) {
    return __fdividef(1.f, 1.f + __expf(-x));
}
__device__ __forceinline__ float tanh_fast(float x) {
    return 1.f - 2.f * __fdividef(1.f, __expf(2.f * x) + 1.f);
}

__global__ __launch_bounds__(128) void gru_layer_kernel(
    float* __restrict__ hA, float* __restrict__ hB,
    const float* __restrict__ Whh, const float* __restrict__ bhh,
    const float* __restrict__ gx,
    float* __restrict__ hseq,
    float* __restrict__ hfin,
    int* __restrict__ flags,
    int write_seq)
{
    extern __shared__ float smem[];
    float* sW = smem;                       // [(g*256+k)*32 + j]
    float* sh = smem + SW_FLOATS;           // [k*16 + m]
    float* sp = sh + SH_FLOATS;             // [((w*3+g)*16+m)*32 + j]

    const int jt = blockIdx.x;
    const int mt = blockIdx.y;
    const int jb = jt * 32;
    const int mb = mt * 16;
    const int tid = threadIdx.x;
    const int wid = tid >> 5;
    const int lane = tid & 31;

    // FMA-loop lane mapping
    const int mq = (lane >> 3) * 4;         // m-quad base
    const int j0 = (lane & 7) * 4;          // j-quad base
    const int k0 = wid * 64;                // K slice

    // reduction mapping: 4 consecutive j per thread
    const int m_r = tid >> 3;               // 0..15
    const int j_r = (tid & 7) * 4;          // 0..28

    // ---- one-time: zero h stage (h(0)=0), load Whh tile ----
    for (int i = tid; i < SH_FLOATS; i += 128) sh[i] = 0.f;
    if (tid < 96) {
        const int g = tid >> 5;
        const int j = tid & 31;
        const float* wrow = Whh + (size_t)(g * HH + jb + j) * HH;
        float* dst = sW + (size_t)g * 256 * 32 + j;
#pragma unroll 4
        for (int k = 0; k < 256; k += 4) {
            float4 v = *(const float4*)(wrow + k);
            dst[(k + 0) * 32] = v.x;
            dst[(k + 1) * 32] = v.y;
            dst[(k + 2) * 32] = v.z;
            dst[(k + 3) * 32] = v.w;
        }
    }

    const float4 br4 = *(const float4*)(bhh + jb + j_r);
    const float4 bz4 = *(const float4*)(bhh + HH + jb + j_r);
    const float4 bn4 = *(const float4*)(bhh + 2 * HH + jb + j_r);

    // h-stage loader mapping
    const int sm_ = tid & 15;
    const int skb = (tid >> 4) * 32;
    const bool stage_mine = ((tid >> 4) != jt);   // skip own chunk

    const int b_r = mb + m_r;
    const float* gxb = gx + (size_t)b_r * TT * G3;
    int* const flagp = flags + mt * 32;     // 128B line per group

    __syncthreads();

    for (int t = 0; t < TT; t++) {
        const float* rb = (t & 1) ? hB : hA;
        float*       wb = (t & 1) ? hA : hB;

        // ---- gx prefetch BEFORE the wait (lands during the spin) ----
        const float* gxp = gxb + (size_t)t * G3;
        const float4 gr4 = __ldg((const float4*)(gxp + jb + j_r));
        const float4 gz4 = __ldg((const float4*)(gxp + HH + jb + j_r));
        const float4 gn4 = __ldg((const float4*)(gxp + 2 * HH + jb + j_r));

        if (t > 0) {
            // all-thread poll; 32 warp-releases per step per group
            {
                const int tgt = 32 * t;
                int v;
                do {
                    asm volatile("ld.global.acquire.gpu.b32 %0, [%1];"
                                 : "=r"(v) : "l"(flagp));
                } while (v < tgt);
            }
            // stage h tile [k][16m], float4 loads, own chunk skipped
            if (stage_mine) {
                const float* src = rb + (size_t)(mb + sm_) * HH + skb;
#pragma unroll
                for (int i = 0; i < 32; i += 4) {
                    const float4 v = __ldcg((const float4*)(src + i));
                    sh[(skb + i + 0) * 16 + sm_] = v.x;
                    sh[(skb + i + 1) * 16 + sm_] = v.y;
                    sh[(skb + i + 2) * 16 + sm_] = v.z;
                    sh[(skb + i + 3) * 16 + sm_] = v.w;
                }
            }
        }
        __syncthreads();

        // ---- warp-split-K FMA loop ----
        ull acc[4][3][2];
#pragma unroll
        for (int m = 0; m < 4; m++)
#pragma unroll
            for (int g = 0; g < 3; g++) {
                acc[m][g][0] = 0ull;
                acc[m][g][1] = 0ull;
            }
        {
            const float* hP  = sh + k0 * 16 + mq;
            const float* w0P = sW + (size_t)(0 * 256 + k0) * 32 + j0;
            const float* w1P = sW + (size_t)(1 * 256 + k0) * 32 + j0;
            const float* w2P = sW + (size_t)(2 * 256 + k0) * 32 + j0;
#pragma unroll 4
            for (int kk = 0; kk < 64; kk++) {
                const float4 hq = *(const float4*)(hP + kk * 16);
                ull h0, h1, h2, h3;
                PACK2(h0, hq.x); PACK2(h1, hq.y);
                PACK2(h2, hq.z); PACK2(h3, hq.w);

                const ull* wr = (const ull*)(w0P + (size_t)kk * 32);
                const ull wr0 = wr[0], wr1 = wr[1];
                FMA2(acc[0][0][0], h0, wr0); FMA2(acc[0][0][1], h0, wr1);
                FMA2(acc[1][0][0], h1, wr0); FMA2(acc[1][0][1], h1, wr1);
                FMA2(acc[2][0][0], h2, wr0); FMA2(acc[2][0][1], h2, wr1);
                FMA2(acc[3][0][0], h3, wr0); FMA2(acc[3][0][1], h3, wr1);

                const ull* wz = (const ull*)(w1P + (size_t)kk * 32);
                const ull wz0 = wz[0], wz1 = wz[1];
                FMA2(acc[0][1][0], h0, wz0); FMA2(acc[0][1][1], h0, wz1);
                FMA2(acc[1][1][0], h1, wz0); FMA2(acc[1][1][1], h1, wz1);
                FMA2(acc[2][1][0], h2, wz0); FMA2(acc[2][1][1], h2, wz1);
                FMA2(acc[3][1][0], h3, wz0); FMA2(acc[3][1][1], h3, wz1);

                const ull* wn = (const ull*)(w2P + (size_t)kk * 32);
                const ull wn0 = wn[0], wn1 = wn[1];
                FMA2(acc[0][2][0], h0, wn0); FMA2(acc[0][2][1], h0, wn1);
                FMA2(acc[1][2][0], h1, wn0); FMA2(acc[1][2][1], h1, wn1);
                FMA2(acc[2][2][0], h2, wn0); FMA2(acc[2][2][1], h2, wn1);
                FMA2(acc[3][2][0], h3, wn0); FMA2(acc[3][2][1], h3, wn1);
            }
        }

        // store partials
#pragma unroll
        for (int m = 0; m < 4; m++) {
#pragma unroll
            for (int g = 0; g < 3; g++) {
                ull* dst = (ull*)(sp + (size_t)(((wid * 3 + g) * 16) + mq + m) * 32 + j0);
                dst[0] = acc[m][g][0];
                dst[1] = acc[m][g][1];
            }
        }
        __syncthreads();   // (A) partials ready; all sh reads done

        // ---- reduce across 4 warps + gates ----
        float ghr[4], ghz[4], ghn[4];
        {
            float4 s0, s1, s2, s3;
            s0 = *(const float4*)(sp + (size_t)((0 * 3 + 0) * 16 + m_r) * 32 + j_r);
            s1 = *(const float4*)(sp + (size_t)((1 * 3 + 0) * 16 + m_r) * 32 + j_r);
            s2 = *(const float4*)(sp + (size_t)((2 * 3 + 0) * 16 + m_r) * 32 + j_r);
            s3 = *(const float4*)(sp + (size_t)((3 * 3 + 0) * 16 + m_r) * 32 + j_r);
            ghr[0] = (s0.x + s1.x) + (s2.x + s3.x);
            ghr[1] = (s0.y + s1.y) + (s2.y + s3.y);
            ghr[2] = (s0.z + s1.z) + (s2.z + s3.z);
            ghr[3] = (s0.w + s1.w) + (s2.w + s3.w);
            s0 = *(const float4*)(sp + (size_t)((0 * 3 + 1) * 16 + m_r) * 32 + j_r);
            s1 = *(const float4*)(sp + (size_t)((1 * 3 + 1) * 16 + m_r) * 32 + j_r);
            s2 = *(const float4*)(sp + (size_t)((2 * 3 + 1) * 16 + m_r) * 32 + j_r);
            s3 = *(const float4*)(sp + (size_t)((3 * 3 + 1) * 16 + m_r) * 32 + j_r);
            ghz[0] = (s0.x + s1.x) + (s2.x + s3.x);
            ghz[1] = (s0.y + s1.y) + (s2.y + s3.y);
            ghz[2] = (s0.z + s1.z) + (s2.z + s3.z);
            ghz[3] = (s0.w + s1.w) + (s2.w + s3.w);
            s0 = *(const float4*)(sp + (size_t)((0 * 3 + 2) * 16 + m_r) * 32 + j_r);
            s1 = *(const float4*)(sp + (size_t)((1 * 3 + 2) * 16 + m_r) * 32 + j_r);
            s2 = *(const float4*)(sp + (size_t)((2 * 3 + 2) * 16 + m_r) * 32 + j_r);
            s3 = *(const float4*)(sp + (size_t)((3 * 3 + 2) * 16 + m_r) * 32 + j_r);
            ghn[0] = (s0.x + s1.x) + (s2.x + s3.x);
            ghn[1] = (s0.y + s1.y) + (s2.y + s3.y);
            ghn[2] = (s0.z + s1.z) + (s2.z + s3.z);
            ghn[3] = (s0.w + s1.w) + (s2.w + s3.w);
        }

        const float grr[4] = {gr4.x, gr4.y, gr4.z, gr4.w};
        const float gzz[4] = {gz4.x, gz4.y, gz4.z, gz4.w};
        const float gnn[4] = {gn4.x, gn4.y, gn4.z, gn4.w};
        const float brr[4] = {br4.x, br4.y, br4.z, br4.w};
        const float bzz[4] = {bz4.x, bz4.y, bz4.z, bz4.w};
        const float bnn[4] = {bn4.x, bn4.y, bn4.z, bn4.w};

        float hnew[4];
#pragma unroll
        for (int ji = 0; ji < 4; ji++) {
            const float ho = sh[(jb + j_r + ji) * 16 + m_r];
            const float r = sigm(grr[ji] + ghr[ji] + brr[ji]);
            const float z = sigm(gzz[ji] + ghz[ji] + bzz[ji]);
            const float n = tanh_fast(gnn[ji] + r * (ghn[ji] + bnn[ji]));
            hnew[ji] = (1.f - z) * n + z * ho;
        }

        // own chunk straight into sh for next step (same slot, same thread)
#pragma unroll
        for (int ji = 0; ji < 4; ji++)
            sh[(jb + j_r + ji) * 16 + m_r] = hnew[ji];

        // publish slice via L2 for peer CTAs
        {
            float* dst = wb + (size_t)b_r * HH + jb + j_r;
            asm volatile("st.global.cg.v4.f32 [%0], {%1,%2,%3,%4};"
                         :: "l"(dst), "f"(hnew[0]), "f"(hnew[1]),
                            "f"(hnew[2]), "f"(hnew[3]));
        }

        // per-warp release: no block barrier on the critical path
        __syncwarp();
        if (lane == 0) {
            asm volatile("red.release.gpu.global.add.u32 [%0], %1;"
                         :: "l"(flagp), "r"(1) : "memory");
        }

        // off-critical-path outputs
        if (write_seq) {
            float4 hv4;
            hv4.x = hnew[0]; hv4.y = hnew[1]; hv4.z = hnew[2]; hv4.w = hnew[3];
            *(float4*)(hseq + ((size_t)b_r * TT + t) * HH + jb + j_r) = hv4;
        }
        if (t == TT - 1) {
            float4 hv4;
            hv4.x = hnew[0]; hv4.y = hnew[1]; hv4.z = hnew[2]; hv4.w = hnew[3];
            *(float4*)(hfin + (size_t)b_r * HH + jb + j_r) = hv4;
        }
    }
}

// ---------------------------------------------------------------------------
// Final FC
// ---------------------------------------------------------------------------
__global__ __launch_bounds__(128) void fc_kernel(
    const float* __restrict__ hfin, const float* __restrict__ W,
    const float* __restrict__ bias, float* __restrict__ out)
{
    __shared__ float hs[HH];
    const int b = blockIdx.x;
    const float* hrow = hfin + (size_t)b * HH;
    for (int i = threadIdx.x; i < HH; i += 128) hs[i] = hrow[i];
    __syncthreads();
    const int o = threadIdx.x;
    if (o < OUTD) {
        float acc = bias[o];
        const float* wr = W + (size_t)o * HH;
#pragma unroll 8
        for (int k = 0; k < HH; k++) acc += hs[k] * wr[k];
        out[(size_t)b * OUTD + o] = acc;
    }
}

// ---------------------------------------------------------------------------
extern "C" void kernel_launch(void* const* d_in, const int* in_sizes, int n_in,
                              void* d_out, int out_size)
{
    const float* x    = (const float*)d_in[0];
    const float* Wih0 = (const float*)d_in[1];
    const float* Whh0 = (const float*)d_in[2];
    const float* bih0 = (const float*)d_in[3];
    const float* bhh0 = (const float*)d_in[4];
    const float* Wih1 = (const float*)d_in[5];
    const float* Whh1 = (const float*)d_in[6];
    const float* bih1 = (const float*)d_in[7];
    const float* bhh1 = (const float*)d_in[8];
    const float* fcW  = (const float*)d_in[9];
    const float* fcb  = (const float*)d_in[10];
    float* out = (float*)d_out;

    float *gx, *hseq, *hA, *hB, *hfin;
    int* flags;
    cudaGetSymbolAddress((void**)&gx, g_gx);
    cudaGetSymbolAddress((void**)&hseq, g_hseq);
    cudaGetSymbolAddress((void**)&hA, g_hA);
    cudaGetSymbolAddress((void**)&hB, g_hB);
    cudaGetSymbolAddress((void**)&hfin, g_hfin);
    cudaGetSymbolAddress((void**)&flags, g_flags);

    static bool attr_set = false;
    if (!attr_set) {
        cudaFuncSetAttribute(gru_layer_kernel,
                             cudaFuncAttributeMaxDynamicSharedMemorySize,
                             LAYER_SMEM_FLOATS * (int)sizeof(float));
        cudaFuncSetAttribute(gemm_tf32_kernel,
                             cudaFuncAttributeMaxDynamicSharedMemorySize,
                             64 * 1024);
        attr_set = true;
    }

    const dim3 gemmGrid(G3 / 128, (BATCH * TT) / 128);
    const dim3 layerGrid(8, 16);
    const int layerSmem = LAYER_SMEM_FLOATS * (int)sizeof(float);
    const int gemmSmem = 64 * 1024;

    // ---- layer 0 ----
    gemm_tf32_kernel<<<gemmGrid, 256, gemmSmem>>>(x, Wih0, bih0, gx, BATCH * TT, DIN);
    cudaMemsetAsync(flags, 0, 16 * 32 * sizeof(int));
    gru_layer_kernel<<<layerGrid, 128, layerSmem>>>(
        hA, hB, Whh0, bhh0, gx, hseq, hfin, flags, 1);

    // ---- layer 1 (no hseq; final h -> hfin) ----
    gemm_tf32_kernel<<<gemmGrid, 256, gemmSmem>>>(hseq, Wih1, bih1, gx, BATCH * TT, HH);
    cudaMemsetAsync(flags, 0, 16 * 32 * sizeof(int));
    gru_layer_kernel<<<layerGrid, 128, layerSmem>>>(
        hA, hB, Whh1, bhh1, gx, hseq, hfin, flags, 0);

    // ---- final FC ----
    fc_kernel<<<BATCH, 128>>>(hfin, fcW, fcb, out);
}